// round 1
// baseline (speedup 1.0000x reference)
#include <cuda_runtime.h>

#define IN_C   256
#define OUT_C  128
#define NHEAD  4
#define MAX_N  131072
#define MAX_C  1024   // scan kernel supports up to 1024 classes (problem uses 1000)

// Scratch (static __device__ globals: allocation-free per harness rules)
__device__ float g_v[NHEAD * IN_C];   // v[h][k] = sum_o W_lin[h*128+o][k] * W_att[o]
__device__ float g_c[NHEAD];          // c[h]    = sum_o b_lin[h*128+o] * W_att[o] + b_att
__device__ int   g_count[MAX_C];
__device__ int   g_offset[MAX_C + 1];
__device__ int   g_cursor[MAX_C];
__device__ int   g_sorted[MAX_N];

// ---------------------------------------------------------------------------
// K1: precompute v, c; zero histogram. grid = NHEAD blocks x 256 threads.
// ---------------------------------------------------------------------------
__global__ void k_prep(const float* __restrict__ W_lin,
                       const float* __restrict__ b_lin,
                       const float* __restrict__ W_att,
                       const float* __restrict__ b_att,
                       int num_classes) {
    const int h = blockIdx.x;
    const int t = threadIdx.x;

    if (h == 0) {
        for (int i = t; i < num_classes; i += 256) g_count[i] = 0;
    }

    // v[h][t] = sum_o W_lin[(h*OUT_C+o)*IN_C + t] * W_att[o]
    float s = 0.0f;
#pragma unroll 4
    for (int o = 0; o < OUT_C; ++o) {
        s += W_lin[(size_t)(h * OUT_C + o) * IN_C + t] * __ldg(&W_att[o]);
    }
    g_v[h * IN_C + t] = s;

    // c[h] by warp 0 of each block
    if (t < 32) {
        float cs = 0.0f;
        for (int o = t; o < OUT_C; o += 32)
            cs += b_lin[h * OUT_C + o] * W_att[o];
#pragma unroll
        for (int d = 16; d; d >>= 1)
            cs += __shfl_xor_sync(0xffffffffu, cs, d);
        if (t == 0) g_c[h] = cs + b_att[0];
    }
}

// ---------------------------------------------------------------------------
// K2: class histogram
// ---------------------------------------------------------------------------
__global__ void k_hist(const int* __restrict__ y, int n) {
    int i = blockIdx.x * blockDim.x + threadIdx.x;
    if (i < n) atomicAdd(&g_count[y[i]], 1);
}

// ---------------------------------------------------------------------------
// K3: exclusive scan of counts (single block, num_classes <= 1024)
// ---------------------------------------------------------------------------
__global__ void k_scan(int num_classes, int n) {
    __shared__ int sm[1024];
    const int t = threadIdx.x;
    int val = (t < num_classes) ? g_count[t] : 0;
    sm[t] = val;
    __syncthreads();
#pragma unroll
    for (int d = 1; d < 1024; d <<= 1) {
        int x = (t >= d) ? sm[t - d] : 0;
        __syncthreads();
        sm[t] += x;
        __syncthreads();
    }
    if (t < num_classes) {
        int off = sm[t] - val;   // exclusive
        g_offset[t] = off;
        g_cursor[t] = off;
    }
    if (t == num_classes - 1) g_offset[num_classes] = sm[t];
    (void)n;
}

// ---------------------------------------------------------------------------
// K4: scatter indices into class-sorted order
// ---------------------------------------------------------------------------
__global__ void k_scatter(const int* __restrict__ y, int n) {
    int i = blockIdx.x * blockDim.x + threadIdx.x;
    if (i < n) {
        int pos = atomicAdd(&g_cursor[y[i]], 1);
        g_sorted[pos] = i;
    }
}

// ---------------------------------------------------------------------------
// K5: fused score + softmax + weighted pooling. One block per class.
//   - each warp handles members round-robin (i = beg + warp, step 8)
//   - per member: load 1KB row (2x LDG.128/lane), 4 dot products,
//     warp-shuffle reduce, exp, accumulate into register accumulators
//   - final: cross-warp reduce via smem, divide by denom, store
// ---------------------------------------------------------------------------
__global__ __launch_bounds__(256) void k_pool(const float* __restrict__ H,
                                              float* __restrict__ out,
                                              int num_classes) {
    const int cls  = blockIdx.x;
    const int tid  = threadIdx.x;
    const int warp = tid >> 5;
    const int lane = tid & 31;

    const int beg = g_offset[cls];
    const int end = g_offset[cls + 1];

    // column ownership: lane owns cols [4*lane .. 4*lane+3] and [128+4*lane ..]
    const int ca = lane * 4;
    const int cb = 128 + lane * 4;

    // load v into registers: 4 heads x 8 cols
    float v0[NHEAD][4], v1[NHEAD][4];
#pragma unroll
    for (int h = 0; h < NHEAD; ++h) {
        float4 a = *(const float4*)&g_v[h * IN_C + ca];
        float4 b = *(const float4*)&g_v[h * IN_C + cb];
        v0[h][0] = a.x; v0[h][1] = a.y; v0[h][2] = a.z; v0[h][3] = a.w;
        v1[h][0] = b.x; v1[h][1] = b.y; v1[h][2] = b.z; v1[h][3] = b.w;
    }
    float cbias[NHEAD];
#pragma unroll
    for (int h = 0; h < NHEAD; ++h) cbias[h] = g_c[h];

    float acc0[NHEAD][4], acc1[NHEAD][4], dsum[NHEAD];
#pragma unroll
    for (int h = 0; h < NHEAD; ++h) {
        dsum[h] = 0.0f;
#pragma unroll
        for (int j = 0; j < 4; ++j) { acc0[h][j] = 0.0f; acc1[h][j] = 0.0f; }
    }

    for (int i = beg + warp; i < end; i += 8) {
        const int n = g_sorted[i];
        const float* row = H + (size_t)n * IN_C;
        const float4 r0 = *(const float4*)(row + ca);
        const float4 r1 = *(const float4*)(row + cb);

        float s[NHEAD];
#pragma unroll
        for (int h = 0; h < NHEAD; ++h) {
            s[h] =  r0.x * v0[h][0] + r0.y * v0[h][1]
                  + r0.z * v0[h][2] + r0.w * v0[h][3]
                  + r1.x * v1[h][0] + r1.y * v1[h][1]
                  + r1.z * v1[h][2] + r1.w * v1[h][3];
        }
#pragma unroll
        for (int h = 0; h < NHEAD; ++h) {
#pragma unroll
            for (int d = 16; d; d >>= 1)
                s[h] += __shfl_xor_sync(0xffffffffu, s[h], d);
        }
#pragma unroll
        for (int h = 0; h < NHEAD; ++h) {
            float sc = s[h] + cbias[h];
            sc = (sc >= 0.0f) ? sc : 0.2f * sc;           // leaky_relu(0.2)
            const float e = __expf(sc);                    // scores are tiny: no max needed
            dsum[h] += e;
            acc0[h][0] += e * r0.x; acc0[h][1] += e * r0.y;
            acc0[h][2] += e * r0.z; acc0[h][3] += e * r0.w;
            acc1[h][0] += e * r1.x; acc1[h][1] += e * r1.y;
            acc1[h][2] += e * r1.z; acc1[h][3] += e * r1.w;
        }
    }

    // cross-warp reduction via smem
    __shared__ float s_acc[8 * NHEAD * IN_C];   // 32 KB
    __shared__ float s_den[8 * NHEAD];
#pragma unroll
    for (int h = 0; h < NHEAD; ++h) {
        float* base = &s_acc[(warp * NHEAD + h) * IN_C];
        *(float4*)(base + ca) = make_float4(acc0[h][0], acc0[h][1], acc0[h][2], acc0[h][3]);
        *(float4*)(base + cb) = make_float4(acc1[h][0], acc1[h][1], acc1[h][2], acc1[h][3]);
        if (lane == 0) s_den[warp * NHEAD + h] = dsum[h];
    }
    __syncthreads();

    float den[NHEAD];
#pragma unroll
    for (int h = 0; h < NHEAD; ++h) {
        float d = 0.0f;
#pragma unroll
        for (int w = 0; w < 8; ++w) d += s_den[w * NHEAD + h];
        den[h] = d;
    }
#pragma unroll
    for (int h = 0; h < NHEAD; ++h) {
        float a = 0.0f;
#pragma unroll
        for (int w = 0; w < 8; ++w) a += s_acc[(w * NHEAD + h) * IN_C + tid];
        out[(size_t)cls * (NHEAD * IN_C) + h * IN_C + tid] =
            (den[h] > 0.0f) ? (a / den[h]) : 0.0f;
    }
}

// ---------------------------------------------------------------------------
extern "C" void kernel_launch(void* const* d_in, const int* in_sizes, int n_in,
                              void* d_out, int out_size) {
    const float* H     = (const float*)d_in[0];   // context_h [N, 256]
    const float* W_lin = (const float*)d_in[1];   // [512, 256]
    const float* b_lin = (const float*)d_in[2];   // [512]
    const float* W_att = (const float*)d_in[3];   // [128]
    const float* b_att = (const float*)d_in[4];   // [1]
    const int*   y     = (const int*)d_in[5];     // [N]
    float*       out   = (float*)d_out;

    const int N = in_sizes[0] / IN_C;
    const int num_classes = out_size / (NHEAD * IN_C);

    k_prep<<<NHEAD, 256>>>(W_lin, b_lin, W_att, b_att, num_classes);
    k_hist<<<(N + 255) / 256, 256>>>(y, N);
    k_scan<<<1, 1024>>>(num_classes, N);
    k_scatter<<<(N + 255) / 256, 256>>>(y, N);
    k_pool<<<num_classes, 256>>>(H, out, num_classes);
    (void)n_in;
}

// round 2
// speedup vs baseline: 1.0724x; 1.0724x over previous
#include <cuda_runtime.h>

#define IN_C   256
#define OUT_C  128
#define NHEAD  4
#define MAX_N  131072
#define MAX_C  1024
#define TILE   64

// Scratch (static __device__ globals: allocation-free per harness rules)
__device__ float g_v[NHEAD * IN_C];
__device__ float g_c[NHEAD];
__device__ int   g_count[MAX_C];
__device__ int   g_offset[MAX_C + 1];
__device__ int   g_cursor[MAX_C];
__device__ int   g_sorted[MAX_N];

// ---------------------------------------------------------------------------
// K1: precompute v, c; zero histogram.
// ---------------------------------------------------------------------------
__global__ void k_prep(const float* __restrict__ W_lin,
                       const float* __restrict__ b_lin,
                       const float* __restrict__ W_att,
                       const float* __restrict__ b_att,
                       int num_classes) {
    const int h = blockIdx.x;
    const int t = threadIdx.x;

    if (h == 0) {
        for (int i = t; i < num_classes; i += 256) g_count[i] = 0;
    }

    float s = 0.0f;
#pragma unroll 4
    for (int o = 0; o < OUT_C; ++o) {
        s += W_lin[(size_t)(h * OUT_C + o) * IN_C + t] * __ldg(&W_att[o]);
    }
    g_v[h * IN_C + t] = s;

    if (t < 32) {
        float cs = 0.0f;
        for (int o = t; o < OUT_C; o += 32)
            cs += b_lin[h * OUT_C + o] * W_att[o];
#pragma unroll
        for (int d = 16; d; d >>= 1)
            cs += __shfl_xor_sync(0xffffffffu, cs, d);
        if (t == 0) g_c[h] = cs + b_att[0];
    }
}

// ---------------------------------------------------------------------------
// K2: class histogram
// ---------------------------------------------------------------------------
__global__ void k_hist(const int* __restrict__ y, int n) {
    int i = blockIdx.x * blockDim.x + threadIdx.x;
    if (i < n) atomicAdd(&g_count[y[i]], 1);
}

// ---------------------------------------------------------------------------
// K3: exclusive scan of counts (single block)
// ---------------------------------------------------------------------------
__global__ void k_scan(int num_classes, int n) {
    __shared__ int sm[1024];
    const int t = threadIdx.x;
    int val = (t < num_classes) ? g_count[t] : 0;
    sm[t] = val;
    __syncthreads();
#pragma unroll
    for (int d = 1; d < 1024; d <<= 1) {
        int x = (t >= d) ? sm[t - d] : 0;
        __syncthreads();
        sm[t] += x;
        __syncthreads();
    }
    if (t < num_classes) {
        int off = sm[t] - val;
        g_offset[t] = off;
        g_cursor[t] = off;
    }
    if (t == num_classes - 1) g_offset[num_classes] = sm[t];
    (void)n;
}

// ---------------------------------------------------------------------------
// K4: scatter indices into class-sorted order
// ---------------------------------------------------------------------------
__global__ void k_scatter(const int* __restrict__ y, int n) {
    int i = blockIdx.x * blockDim.x + threadIdx.x;
    if (i < n) {
        int pos = atomicAdd(&g_cursor[y[i]], 1);
        g_sorted[pos] = i;
    }
}

// ---------------------------------------------------------------------------
// K5 v2: smem-tiled fused score+softmax+pool. One block per class.
//
// Dynamic smem layout (floats):
//   sv   [0,1024)        : v weights [4][256]
//   part [1024,2048)     : score partials [q=4][r=64][h=4]
//   se   [2048,2304)     : e[r=64][h=4]
//   sdr  [2304,2560)     : denom partials [r=64][h=4]
//   rows [2560,+16384)   : staged tile, row r at rows[r*256], float4 chunk c
//                          stored at chunk (c ^ (r&7))  (XOR swizzle)
// rows region reused as red[rg=4][h=4][col=256] for final reduction.
// ---------------------------------------------------------------------------
__global__ void __launch_bounds__(256) k_pool(const float* __restrict__ H,
                                              float* __restrict__ out,
                                              int num_classes) {
    extern __shared__ float smf[];
    float* sv   = smf;
    float* part = smf + 1024;
    float* se   = smf + 2048;
    float* sdr  = smf + 2304;
    float* rows = smf + 2560;

    float4*       rows4 = (float4*)rows;
    const float4* sv4   = (const float4*)sv;
    const float4* se4   = (const float4*)se;

    const int tid  = threadIdx.x;
    const int cls  = blockIdx.x;
    const int warp = tid >> 5;
    const int lane = tid & 31;
    const int q    = tid >> 6;   // score phase: col quadrant
    const int rS   = tid & 63;   // score phase: row
    const int cg   = tid & 63;   // acc phase: float4 col chunk
    const int rg   = tid >> 6;   // acc phase: row group (16 rows)

    const int beg = g_offset[cls];
    const int cnt = g_offset[cls + 1] - beg;

    // stage v into smem
    for (int i = tid; i < NHEAD * IN_C; i += 256) sv[i] = g_v[i];
    float cb[NHEAD];
#pragma unroll
    for (int h = 0; h < NHEAD; ++h) cb[h] = g_c[h];

    float acc[NHEAD][4];
    float dsum[NHEAD];
#pragma unroll
    for (int h = 0; h < NHEAD; ++h) {
        dsum[h] = 0.0f;
#pragma unroll
        for (int j = 0; j < 4; ++j) acc[h][j] = 0.0f;
    }

    __syncthreads();

    for (int t0 = 0; t0 < cnt; t0 += TILE) {
        // ---- stage: warp w copies rows [w*8, w*8+8) (zero-fill past cnt) ----
#pragma unroll
        for (int rr = 0; rr < 8; ++rr) {
            const int r  = warp * 8 + rr;
            const int gi = t0 + r;
            // lane handles chunks lane and lane+32 (XOR-swizzled dest)
            const int d0 = r * 64 + (lane ^ (r & 7));
            const int d1 = r * 64 + ((lane + 32) ^ (r & 7));
            if (gi < cnt) {
                const float4* src =
                    (const float4*)(H + (size_t)g_sorted[beg + gi] * IN_C);
                rows4[d0] = src[lane];
                rows4[d1] = src[lane + 32];
            } else {
                const float4 z = make_float4(0.f, 0.f, 0.f, 0.f);
                rows4[d0] = z;
                rows4[d1] = z;
            }
        }
        __syncthreads();

        // ---- score partials: thread (q, rS) covers cols [q*64, q*64+64) ----
        {
            float s[NHEAD] = {0.f, 0.f, 0.f, 0.f};
            const int rbase = rS * 64;
            const int sw    = rS & 7;
#pragma unroll
            for (int j = 0; j < 16; ++j) {
                const float4 x = rows4[rbase + ((q * 16 + j) ^ sw)];
#pragma unroll
                for (int h = 0; h < NHEAD; ++h) {
                    const float4 vv = sv4[h * 64 + q * 16 + j];
                    s[h] += x.x * vv.x + x.y * vv.y + x.z * vv.z + x.w * vv.w;
                }
            }
            float4* p4 = (float4*)&part[(q * 64 + rS) * 4];
            *p4 = make_float4(s[0], s[1], s[2], s[3]);
        }
        __syncthreads();

        // ---- reduce partials -> e[r][h] (threads 0..63) ----
        if (tid < 64) {
            const bool valid = (t0 + tid) < cnt;
            float4 p0 = *(const float4*)&part[(0 * 64 + tid) * 4];
            float4 p1 = *(const float4*)&part[(1 * 64 + tid) * 4];
            float4 p2 = *(const float4*)&part[(2 * 64 + tid) * 4];
            float4 p3 = *(const float4*)&part[(3 * 64 + tid) * 4];
            float s[NHEAD];
            s[0] = p0.x + p1.x + p2.x + p3.x;
            s[1] = p0.y + p1.y + p2.y + p3.y;
            s[2] = p0.z + p1.z + p2.z + p3.z;
            s[3] = p0.w + p1.w + p2.w + p3.w;
            float e[NHEAD];
#pragma unroll
            for (int h = 0; h < NHEAD; ++h) {
                float sc = s[h] + cb[h];
                sc = (sc >= 0.0f) ? sc : 0.2f * sc;   // leaky_relu(0.2)
                e[h] = valid ? __expf(sc) : 0.0f;     // tiny scores: exp-ratio safe
                dsum[h] += e[h];
            }
            *(float4*)&se[tid * 4] = make_float4(e[0], e[1], e[2], e[3]);
        }
        __syncthreads();

        // ---- accumulate: thread (cg, rg) does 16 rows x 4 cols x 4 heads ----
#pragma unroll
        for (int rr = 0; rr < 16; ++rr) {
            const int    r = rg * 16 + rr;
            const float4 x = rows4[r * 64 + (cg ^ (r & 7))];
            const float4 e = se4[r];
            acc[0][0] += e.x * x.x; acc[0][1] += e.x * x.y;
            acc[0][2] += e.x * x.z; acc[0][3] += e.x * x.w;
            acc[1][0] += e.y * x.x; acc[1][1] += e.y * x.y;
            acc[1][2] += e.y * x.z; acc[1][3] += e.y * x.w;
            acc[2][0] += e.z * x.x; acc[2][1] += e.z * x.y;
            acc[2][2] += e.z * x.z; acc[2][3] += e.z * x.w;
            acc[3][0] += e.w * x.x; acc[3][1] += e.w * x.y;
            acc[3][2] += e.w * x.z; acc[3][3] += e.w * x.w;
        }
        __syncthreads();   // protect rows/se before next tile's staging
    }

    // ---- final reduction across row-groups ----
    // write denom partials
    if (tid < 64) {
        *(float4*)&sdr[tid * 4] = make_float4(dsum[0], dsum[1], dsum[2], dsum[3]);
    }
    // write acc partials into rows region: red[rg][h][col]
    float* red = rows;
#pragma unroll
    for (int h = 0; h < NHEAD; ++h) {
#pragma unroll
        for (int j = 0; j < 4; ++j) {
            red[(rg * NHEAD + h) * IN_C + cg * 4 + j] = acc[h][j];
        }
    }
    __syncthreads();

    // denom reduce: threads 0..3, one head each -> part[h]
    if (tid < NHEAD) {
        float d = 0.0f;
        for (int r = 0; r < 64; ++r) d += sdr[r * 4 + tid];
        part[tid] = d;
    }
    __syncthreads();

    const int col = tid;
#pragma unroll
    for (int h = 0; h < NHEAD; ++h) {
        const float den = part[h];
        float s = red[(0 * NHEAD + h) * IN_C + col]
                + red[(1 * NHEAD + h) * IN_C + col]
                + red[(2 * NHEAD + h) * IN_C + col]
                + red[(3 * NHEAD + h) * IN_C + col];
        out[(size_t)cls * (NHEAD * IN_C) + h * IN_C + col] =
            (den > 0.0f) ? (s / den) : 0.0f;
    }
    (void)num_classes;
}

// ---------------------------------------------------------------------------
extern "C" void kernel_launch(void* const* d_in, const int* in_sizes, int n_in,
                              void* d_out, int out_size) {
    const float* H     = (const float*)d_in[0];
    const float* W_lin = (const float*)d_in[1];
    const float* b_lin = (const float*)d_in[2];
    const float* W_att = (const float*)d_in[3];
    const float* b_att = (const float*)d_in[4];
    const int*   y     = (const int*)d_in[5];
    float*       out   = (float*)d_out;

    const int N = in_sizes[0] / IN_C;
    const int num_classes = out_size / (NHEAD * IN_C);

    const int smem_bytes = (2560 + TILE * IN_C) * (int)sizeof(float);  // 75776
    cudaFuncSetAttribute(k_pool, cudaFuncAttributeMaxDynamicSharedMemorySize,
                         smem_bytes);

    k_prep<<<NHEAD, 256>>>(W_lin, b_lin, W_att, b_att, num_classes);
    k_hist<<<(N + 255) / 256, 256>>>(y, N);
    k_scan<<<1, 1024>>>(num_classes, N);
    k_scatter<<<(N + 255) / 256, 256>>>(y, N);
    k_pool<<<num_classes, 256, smem_bytes>>>(H, out, num_classes);
    (void)n_in;
}

// round 3
// speedup vs baseline: 1.3747x; 1.2819x over previous
#include <cuda_runtime.h>
#include <cstdint>

#define IN_C   256
#define OUT_C  128
#define NHEAD  4
#define MAX_N  131072
#define MAX_C  1024
#define TILE   32
#define CHUNK  256
#define HIST_ITEMS 4096

// Scratch (static __device__ globals: allocation-free per harness rules)
__device__ float g_v[NHEAD * IN_C];
__device__ float g_c[NHEAD];
__device__ int   g_count[MAX_C];
__device__ int   g_offset[MAX_C + 1];
__device__ int   g_cursor[MAX_C];
__device__ int   g_sorted[MAX_N];

// ---------------------------------------------------------------------------
// cp.async helpers (16B, L2 path, zero-fill when sz==0)
// ---------------------------------------------------------------------------
__device__ __forceinline__ void cp_async16(uint32_t dst_sa, const void* src, int sz) {
    asm volatile("cp.async.cg.shared.global [%0], [%1], 16, %2;"
                 :: "r"(dst_sa), "l"(src), "r"(sz));
}
__device__ __forceinline__ void cp_commit() {
    asm volatile("cp.async.commit_group;");
}
template <int N>
__device__ __forceinline__ void cp_wait() {
    asm volatile("cp.async.wait_group %0;" :: "n"(N));
}

// ---------------------------------------------------------------------------
// K1: fused prep (blocks 0..3) + smem-privatized histogram (blocks 4..)
// g_count must be zeroed beforehand (cudaMemsetAsync node).
// ---------------------------------------------------------------------------
__global__ __launch_bounds__(256) void k_prep_hist(
        const float* __restrict__ W_lin,
        const float* __restrict__ b_lin,
        const float* __restrict__ W_att,
        const float* __restrict__ b_att,
        const int* __restrict__ y,
        int n, int num_classes) {
    const int t = threadIdx.x;

    if (blockIdx.x < NHEAD) {
        const int h = blockIdx.x;
        float s = 0.0f;
#pragma unroll 4
        for (int o = 0; o < OUT_C; ++o) {
            s += W_lin[(size_t)(h * OUT_C + o) * IN_C + t] * __ldg(&W_att[o]);
        }
        g_v[h * IN_C + t] = s;

        if (t < 32) {
            float cs = 0.0f;
            for (int o = t; o < OUT_C; o += 32)
                cs += b_lin[h * OUT_C + o] * W_att[o];
#pragma unroll
            for (int d = 16; d; d >>= 1)
                cs += __shfl_xor_sync(0xffffffffu, cs, d);
            if (t == 0) g_c[h] = cs + b_att[0];
        }
        return;
    }

    // histogram role
    __shared__ int scnt[MAX_C];
    for (int c = t; c < num_classes; c += 256) scnt[c] = 0;
    __syncthreads();

    const int base = (blockIdx.x - NHEAD) * HIST_ITEMS;
#pragma unroll
    for (int k = 0; k < HIST_ITEMS / 256; ++k) {
        const int i = base + k * 256 + t;
        if (i < n) atomicAdd(&scnt[y[i]], 1);
    }
    __syncthreads();

    for (int c = t; c < num_classes; c += 256) {
        const int v = scnt[c];
        if (v) atomicAdd(&g_count[c], v);
    }
}

// ---------------------------------------------------------------------------
// K2: exclusive scan of counts (single block)
// ---------------------------------------------------------------------------
__global__ void k_scan(int num_classes) {
    __shared__ int sm[1024];
    const int t = threadIdx.x;
    int val = (t < num_classes) ? g_count[t] : 0;
    sm[t] = val;
    __syncthreads();
#pragma unroll
    for (int d = 1; d < 1024; d <<= 1) {
        int x = (t >= d) ? sm[t - d] : 0;
        __syncthreads();
        sm[t] += x;
        __syncthreads();
    }
    if (t < num_classes) {
        int off = sm[t] - val;
        g_offset[t] = off;
        g_cursor[t] = off;
    }
    if (t == num_classes - 1) g_offset[num_classes] = sm[t];
}

// ---------------------------------------------------------------------------
// K3: two-level scatter. Block handles 4096 items: smem histogram ->
// one global reservation per present class -> smem-cursor local scatter.
// ---------------------------------------------------------------------------
__global__ __launch_bounds__(256) void k_scatter(const int* __restrict__ y,
                                                 int n, int num_classes) {
    __shared__ int scur[MAX_C];
    const int t = threadIdx.x;
    const int base = blockIdx.x * HIST_ITEMS;

    for (int c = t; c < num_classes; c += 256) scur[c] = 0;
    __syncthreads();

    int yv[HIST_ITEMS / 256];
#pragma unroll
    for (int k = 0; k < HIST_ITEMS / 256; ++k) {
        const int i = base + k * 256 + t;
        yv[k] = (i < n) ? y[i] : -1;
        if (yv[k] >= 0) atomicAdd(&scur[yv[k]], 1);
    }
    __syncthreads();

    // reserve a slab per present class; scur[c] becomes the running cursor
    for (int c = t; c < num_classes; c += 256) {
        const int v = scur[c];
        if (v) scur[c] = atomicAdd(&g_cursor[c], v);
    }
    __syncthreads();

#pragma unroll
    for (int k = 0; k < HIST_ITEMS / 256; ++k) {
        if (yv[k] >= 0) {
            const int pos = atomicAdd(&scur[yv[k]], 1);
            g_sorted[pos] = base + k * 256 + t;
        }
    }
}

// ---------------------------------------------------------------------------
// K4: fused score+softmax+pool, cp.async double-buffered tiles of 32 rows.
//
// Dynamic smem (floats):
//   sv   [0,1024)      v weights [4][256]
//   part [1024,2048)   score partials [g=8][r=32][h=4]
//   se   [2048,2176)   e[r=32][h=4]
//   sdr  [2176,2304)   denom partials [r=32][h=4]
//   sidx [2304,2560)   class member indices (256-entry window)
//   rows [2560,+16384) two tile buffers, buffer b at float4 offset b*2048;
//                      row r chunk c stored at (c ^ (r&7))  (XOR swizzle)
// rows buffer 0 reused as red[rg=4][h=4][col=256] for the final reduction.
// ---------------------------------------------------------------------------
__global__ void __launch_bounds__(256) k_pool(const float* __restrict__ H,
                                              float* __restrict__ out) {
    extern __shared__ float smf[];
    float* sv   = smf;
    float* part = smf + 1024;
    float* se   = smf + 2048;
    float* sdr  = smf + 2176;
    int*   sidx = (int*)(smf + 2304);
    float* rows = smf + 2560;

    float4*       rows4 = (float4*)rows;
    const float4* sv4   = (const float4*)sv;
    const float4* se4   = (const float4*)se;
    float4*       part4 = (float4*)part;
    const uint32_t rows_sa = (uint32_t)__cvta_generic_to_shared(rows);

    const int tid  = threadIdx.x;
    const int cls  = blockIdx.x;
    const int warp = tid >> 5;
    const int lane = tid & 31;

    const int beg = g_offset[cls];
    const int cnt = g_offset[cls + 1] - beg;

    for (int i = tid; i < NHEAD * IN_C; i += 256) sv[i] = g_v[i];
    float cb[NHEAD];
#pragma unroll
    for (int h = 0; h < NHEAD; ++h) cb[h] = g_c[h];

    float acc[NHEAD][4];
    float dsum[NHEAD];
#pragma unroll
    for (int h = 0; h < NHEAD; ++h) {
        dsum[h] = 0.0f;
#pragma unroll
        for (int j = 0; j < 4; ++j) acc[h][j] = 0.0f;
    }

    for (int c0 = 0; c0 < cnt; c0 += CHUNK) {
        const int chunkN = min(CHUNK, cnt - c0);
        __syncthreads();                       // protect sidx / rows reuse
        if (tid < chunkN) sidx[tid] = g_sorted[beg + c0 + tid];
        __syncthreads();

        const int nt = (chunkN + TILE - 1) / TILE;

        // ---- stage helper (inlined): tile t0 into buffer b ----
        // warp w loads rows [w*4, w*4+4); lane covers chunks lane, lane+32
        {
            const int b = 0, t0 = 0;
#pragma unroll
            for (int rr = 0; rr < 4; ++rr) {
                const int r  = warp * 4 + rr;
                const int gi = t0 + r;
                const bool valid = gi < chunkN;
                const char* src = (const char*)(H +
                    (valid ? (size_t)sidx[gi] * IN_C : (size_t)0));
                const int sz = valid ? 16 : 0;
                const int d0 = b * 2048 + r * 64 + (lane ^ (r & 7));
                const int d1 = b * 2048 + r * 64 + ((lane + 32) ^ (r & 7));
                cp_async16(rows_sa + d0 * 16, src + lane * 16, sz);
                cp_async16(rows_sa + d1 * 16, src + (lane + 32) * 16, sz);
            }
            cp_commit();
        }

        for (int ti = 0; ti < nt; ++ti) {
            const int b = ti & 1;

            if (ti + 1 < nt) {
                const int bn = b ^ 1;
                const int t0 = (ti + 1) * TILE;
#pragma unroll
                for (int rr = 0; rr < 4; ++rr) {
                    const int r  = warp * 4 + rr;
                    const int gi = t0 + r;
                    const bool valid = gi < chunkN;
                    const char* src = (const char*)(H +
                        (valid ? (size_t)sidx[gi] * IN_C : (size_t)0));
                    const int sz = valid ? 16 : 0;
                    const int d0 = bn * 2048 + r * 64 + (lane ^ (r & 7));
                    const int d1 = bn * 2048 + r * 64 + ((lane + 32) ^ (r & 7));
                    cp_async16(rows_sa + d0 * 16, src + lane * 16, sz);
                    cp_async16(rows_sa + d1 * 16, src + (lane + 32) * 16, sz);
                }
                cp_commit();
                cp_wait<1>();   // tile ti resident
            } else {
                cp_wait<0>();
            }
            __syncthreads();

            // ---- score partials: thread (g=tid>>5, r=tid&31), 32 cols ----
            {
                const int g  = tid >> 5;
                const int r  = tid & 31;
                const int sw = r & 7;
                const float4* rb = rows4 + b * 2048 + r * 64;
                float s[NHEAD] = {0.f, 0.f, 0.f, 0.f};
#pragma unroll
                for (int j = 0; j < 8; ++j) {
                    const float4 x = rb[(g * 8 + j) ^ sw];
#pragma unroll
                    for (int h = 0; h < NHEAD; ++h) {
                        const float4 vv = sv4[h * 64 + g * 8 + j];
                        s[h] += x.x * vv.x + x.y * vv.y + x.z * vv.z + x.w * vv.w;
                    }
                }
                part4[g * 32 + r] = make_float4(s[0], s[1], s[2], s[3]);
            }
            __syncthreads();

            // ---- reduce -> e[r][h] (threads 0..31) ----
            if (tid < 32) {
                float4 a = part4[tid];
#pragma unroll
                for (int g = 1; g < 8; ++g) {
                    const float4 p = part4[g * 32 + tid];
                    a.x += p.x; a.y += p.y; a.z += p.z; a.w += p.w;
                }
                const bool valid = (c0 + ti * TILE + tid) < cnt;
                float s[NHEAD] = {a.x, a.y, a.z, a.w};
                float e[NHEAD];
#pragma unroll
                for (int h = 0; h < NHEAD; ++h) {
                    float sc = s[h] + cb[h];
                    sc = (sc >= 0.0f) ? sc : 0.2f * sc;   // leaky_relu(0.2)
                    e[h] = valid ? __expf(sc) : 0.0f;     // tiny scores: ratio-safe
                    dsum[h] += e[h];
                }
                *(float4*)&se[tid * 4] = make_float4(e[0], e[1], e[2], e[3]);
            }
            __syncthreads();

            // ---- accumulate: thread (cg=tid&63, rg=tid>>6), 8 rows ----
            {
                const int cg = tid & 63;
                const int rg = tid >> 6;
                const float4* rb = rows4 + b * 2048;
#pragma unroll
                for (int rr = 0; rr < 8; ++rr) {
                    const int    r = rg * 8 + rr;
                    const float4 x = rb[r * 64 + (cg ^ (r & 7))];
                    const float4 e = se4[r];
                    acc[0][0] += e.x * x.x; acc[0][1] += e.x * x.y;
                    acc[0][2] += e.x * x.z; acc[0][3] += e.x * x.w;
                    acc[1][0] += e.y * x.x; acc[1][1] += e.y * x.y;
                    acc[1][2] += e.y * x.z; acc[1][3] += e.y * x.w;
                    acc[2][0] += e.z * x.x; acc[2][1] += e.z * x.y;
                    acc[2][2] += e.z * x.z; acc[2][3] += e.z * x.w;
                    acc[3][0] += e.w * x.x; acc[3][1] += e.w * x.y;
                    acc[3][2] += e.w * x.z; acc[3][3] += e.w * x.w;
                }
            }
            __syncthreads();   // before next stage / sidx reuse
        }
    }

    // ---- final reduction ----
    if (tid < 32) {
        *(float4*)&sdr[tid * 4] = make_float4(dsum[0], dsum[1], dsum[2], dsum[3]);
    }
    const int cg = tid & 63;
    const int rg = tid >> 6;
    float* red = rows;   // reuse buffer 0 (16KB needed)
#pragma unroll
    for (int h = 0; h < NHEAD; ++h) {
#pragma unroll
        for (int j = 0; j < 4; ++j) {
            red[(rg * NHEAD + h) * IN_C + cg * 4 + j] = acc[h][j];
        }
    }
    __syncthreads();

    if (tid < NHEAD) {
        float d = 0.0f;
        for (int r = 0; r < 32; ++r) d += sdr[r * 4 + tid];
        part[tid] = d;
    }
    __syncthreads();

    const int col = tid;
#pragma unroll
    for (int h = 0; h < NHEAD; ++h) {
        const float den = part[h];
        float s = red[(0 * NHEAD + h) * IN_C + col]
                + red[(1 * NHEAD + h) * IN_C + col]
                + red[(2 * NHEAD + h) * IN_C + col]
                + red[(3 * NHEAD + h) * IN_C + col];
        out[(size_t)cls * (NHEAD * IN_C) + h * IN_C + col] =
            (den > 0.0f) ? (s / den) : 0.0f;
    }
}

// ---------------------------------------------------------------------------
extern "C" void kernel_launch(void* const* d_in, const int* in_sizes, int n_in,
                              void* d_out, int out_size) {
    const float* H     = (const float*)d_in[0];
    const float* W_lin = (const float*)d_in[1];
    const float* b_lin = (const float*)d_in[2];
    const float* W_att = (const float*)d_in[3];
    const float* b_att = (const float*)d_in[4];
    const int*   y     = (const int*)d_in[5];
    float*       out   = (float*)d_out;

    const int N = in_sizes[0] / IN_C;
    const int num_classes = out_size / (NHEAD * IN_C);
    const int hist_blocks = (N + HIST_ITEMS - 1) / HIST_ITEMS;

    void* cnt_ptr = nullptr;
    cudaGetSymbolAddress(&cnt_ptr, g_count);
    cudaMemsetAsync(cnt_ptr, 0, num_classes * sizeof(int));

    const int smem_bytes = (2560 + 2 * TILE * IN_C) * (int)sizeof(float); // 75776
    cudaFuncSetAttribute(k_pool, cudaFuncAttributeMaxDynamicSharedMemorySize,
                         smem_bytes);

    k_prep_hist<<<NHEAD + hist_blocks, 256>>>(W_lin, b_lin, W_att, b_att,
                                              y, N, num_classes);
    k_scan<<<1, 1024>>>(num_classes);
    k_scatter<<<hist_blocks, 256>>>(y, N, num_classes);
    k_pool<<<num_classes, 256, smem_bytes>>>(H, out);
    (void)n_in;
}